// round 10
// baseline (speedup 1.0000x reference)
#include <cuda_runtime.h>

// GroCo loss, fully fused on-GPU.  (v3 — resubmit of v2; R8/R9 container
// failures were broker-level with no kernel-attributable signal.)
//  1) row-normalize aug1, aug2 -> g_n[0], g_n[1]
//  2) pos[i] = dot(n1_i, n2_i) (shared by both loss directions)
//  3) per direction: fused Gram(n@n.T) + running top-10 (diag excluded),
//     j-range split into NCHUNK chunks; both directions in one 2D grid
//  4) per (dir,row): merge partials -> sims[11] = [10 ascending negs, pos];
//     soft odd-even sort forward (55 alphas), backward propagation of the
//     two indicator vectors (= P-column sums without materializing P);
//     BCE terms accumulated into a double scalar
//  5) loss = -S / (4 * 11 * B)
//
// NOTE: __device__ globals are referenced ONLY from device code. Passing
// them as kernel arguments from host binds the host-side shadow variable,
// which on GB300 (ATS) silently "works" against host memory — wrong buffer.

#define BN 8192
#define DD 128
#define NCHUNK 9
#define TPB 256            // threads per gram block == rows per block
#define TILE 64            // j-rows per shared tile
#define NTILES (BN / TILE) // 128

__device__ float  g_n[2][BN * DD];
__device__ float  g_pos[BN];
__device__ float  g_part[2][BN * NCHUNK * 10];
__device__ double g_acc;

// packed fp32x2 FMA (Blackwell): 2 lane-FMAs per instruction
__device__ __forceinline__ void fma2(unsigned long long& acc,
                                     unsigned long long av,
                                     unsigned long long bv) {
    asm("fma.rn.f32x2 %0, %1, %2, %0;" : "+l"(acc) : "l"(av), "l"(bv));
}

// Branchless insert of v into ascending top-10 array t (t[0] = smallest kept).
// Identity when v <= t[0]; correct sorted insert otherwise.
__device__ __forceinline__ void topk_insert10(float (&t)[10], float v) {
#pragma unroll
    for (int k = 0; k < 9; ++k) t[k] = fminf(fmaxf(v, t[k]), t[k + 1]);
    t[9] = fmaxf(v, t[9]);
}

__global__ void zero_kernel() { g_acc = 0.0; }

__global__ void normalize_kernel(const float* __restrict__ x, int dir) {
    int gw   = (blockIdx.x * blockDim.x + threadIdx.x) >> 5;  // one warp per row
    int lane = threadIdx.x & 31;
    if (gw >= BN) return;
    float4 v = reinterpret_cast<const float4*>(x)[gw * (DD / 4) + lane];
    float s = v.x * v.x + v.y * v.y + v.z * v.z + v.w * v.w;
#pragma unroll
    for (int o = 16; o > 0; o >>= 1) s += __shfl_xor_sync(0xffffffffu, s, o);
    float inv = 1.0f / fmaxf(sqrtf(s), 1e-8f);
    float4 o4 = make_float4(v.x * inv, v.y * inv, v.z * inv, v.w * inv);
    reinterpret_cast<float4*>(g_n[dir])[gw * (DD / 4) + lane] = o4;
}

__global__ void pos_kernel() {
    int gw   = (blockIdx.x * blockDim.x + threadIdx.x) >> 5;
    int lane = threadIdx.x & 31;
    if (gw >= BN) return;
    float4 a = reinterpret_cast<const float4*>(g_n[0])[gw * (DD / 4) + lane];
    float4 b = reinterpret_cast<const float4*>(g_n[1])[gw * (DD / 4) + lane];
    float s = a.x * b.x + a.y * b.y + a.z * b.z + a.w * b.w;
#pragma unroll
    for (int o = 16; o > 0; o >>= 1) s += __shfl_xor_sync(0xffffffffu, s, o);
    if (lane == 0) g_pos[gw] = s;
}

// Fused Gram + top-10. One thread owns one anchor row (64 packed f32x2 regs).
// Block iterates its j-chunk in 64-row shared tiles; all lanes read the same
// tile addresses (broadcast LDS, conflict-free). blockIdx.y = direction.
__global__ void __launch_bounds__(TPB, 1)
gram_topk_kernel() {
    int dir   = blockIdx.y;
    const float* __restrict__ n = g_n[dir];
    int rb    = blockIdx.x / NCHUNK;
    int chunk = blockIdx.x - rb * NCHUNK;
    int r     = rb * TPB + threadIdx.x;

    unsigned long long a[DD / 2];
    {
        const unsigned long long* arow =
            reinterpret_cast<const unsigned long long*>(n + (size_t)r * DD);
#pragma unroll
        for (int k = 0; k < DD / 2; ++k) a[k] = arow[k];
    }

    float t[10];
#pragma unroll
    for (int k = 0; k < 10; ++k) t[k] = -1e30f;

    __shared__ unsigned long long tile[TILE * (DD / 2)];  // 32 KB

    int t0 = (chunk * NTILES) / NCHUNK;
    int t1 = ((chunk + 1) * NTILES) / NCHUNK;

    for (int tt = t0; tt < t1; ++tt) {
        int j0 = tt * TILE;
        __syncthreads();
        {   // cooperative tile load: 2048 float4 by 256 threads
            const float4* src = reinterpret_cast<const float4*>(n + (size_t)j0 * DD);
            float4* dst = reinterpret_cast<float4*>(tile);
#pragma unroll
            for (int i = 0; i < (TILE * DD / 4) / TPB; ++i)
                dst[threadIdx.x + i * TPB] = src[threadIdx.x + i * TPB];
        }
        __syncthreads();

#pragma unroll 1
        for (int jj = 0; jj < TILE; jj += 4) {
            const ulonglong2* b0 = reinterpret_cast<const ulonglong2*>(tile + (jj + 0) * (DD / 2));
            const ulonglong2* b1 = reinterpret_cast<const ulonglong2*>(tile + (jj + 1) * (DD / 2));
            const ulonglong2* b2 = reinterpret_cast<const ulonglong2*>(tile + (jj + 2) * (DD / 2));
            const ulonglong2* b3 = reinterpret_cast<const ulonglong2*>(tile + (jj + 3) * (DD / 2));
            unsigned long long acc0 = 0ull, acc1 = 0ull, acc2 = 0ull, acc3 = 0ull;
#pragma unroll
            for (int k = 0; k < DD / 4; ++k) {
                ulonglong2 q0 = b0[k];
                fma2(acc0, a[2 * k], q0.x);
                fma2(acc0, a[2 * k + 1], q0.y);
                ulonglong2 q1 = b1[k];
                fma2(acc1, a[2 * k], q1.x);
                fma2(acc1, a[2 * k + 1], q1.y);
                ulonglong2 q2 = b2[k];
                fma2(acc2, a[2 * k], q2.x);
                fma2(acc2, a[2 * k + 1], q2.y);
                ulonglong2 q3 = b3[k];
                fma2(acc3, a[2 * k], q3.x);
                fma2(acc3, a[2 * k + 1], q3.y);
            }
            float2 f0 = *reinterpret_cast<float2*>(&acc0);
            float2 f1 = *reinterpret_cast<float2*>(&acc1);
            float2 f2 = *reinterpret_cast<float2*>(&acc2);
            float2 f3 = *reinterpret_cast<float2*>(&acc3);
            float v0 = f0.x + f0.y;
            float v1 = f1.x + f1.y;
            float v2 = f2.x + f2.y;
            float v3 = f3.x + f3.y;
            int j = j0 + jj;
            if (v0 > t[0] && (j + 0) != r) topk_insert10(t, v0);
            if (v1 > t[0] && (j + 1) != r) topk_insert10(t, v1);
            if (v2 > t[0] && (j + 2) != r) topk_insert10(t, v2);
            if (v3 > t[0] && (j + 3) != r) topk_insert10(t, v3);
        }
    }

    float* dst = g_part[dir] + ((size_t)r * NCHUNK + chunk) * 10;
#pragma unroll
    for (int k = 0; k < 10; ++k) dst[k] = t[k];
}

// One thread per (direction, row): merge chunk partials -> top-10 ascending,
// append pos_sim, run soft odd-even sort forward, backward-propagate the
// indicator vectors (p_pos = P@e10, p_neg = P@[1..1,0]), accumulate BCE.
__global__ void finalize_kernel() {
    int idx = blockIdx.x * blockDim.x + threadIdx.x;  // 0 .. 2*BN-1
    int dir = idx >> 13;
    int r   = idx & (BN - 1);
    const float* part = g_part[dir];

    float t[10];
#pragma unroll
    for (int k = 0; k < 10; ++k) t[k] = -1e30f;
    const float* p = part + (size_t)r * (NCHUNK * 10);
    for (int k = 0; k < NCHUNK * 10; ++k) topk_insert10(t, p[k]);

    float s[11];
#pragma unroll
    for (int k = 0; k < 10; ++k) s[k] = t[k];
    s[10] = g_pos[r];

    const float INV_PI = 0.3183098861837907f;
    float alpha[55];
    // forward: 11 layers of odd-even compare-exchange (steepness = 1)
#pragma unroll
    for (int layer = 0; layer < 11; ++layer) {
        int off = layer & 1;
#pragma unroll
        for (int pi = 0; pi < 5; ++pi) {
            int ia = off + 2 * pi, ib = ia + 1;
            float av = s[ia], bv = s[ib];
            float al = atanf(bv - av) * INV_PI + 0.5f;
            alpha[layer * 5 + pi] = al;
            s[ia] = al * av + (1.0f - al) * bv;
            s[ib] = (1.0f - al) * av + al * bv;
        }
    }

    // backward: w <- M_layer w, layers in reverse
    float wp[11], wn[11];
#pragma unroll
    for (int k = 0; k < 11; ++k) { wp[k] = 0.0f; wn[k] = 1.0f; }
    wp[10] = 1.0f; wn[10] = 0.0f;
#pragma unroll
    for (int layer = 10; layer >= 0; --layer) {
        int off = layer & 1;
#pragma unroll
        for (int pi = 0; pi < 5; ++pi) {
            int ia = off + 2 * pi, ib = ia + 1;
            float al = alpha[layer * 5 + pi];
            float pa = wp[ia], pb = wp[ib];
            wp[ia] = al * pa + (1.0f - al) * pb;
            wp[ib] = (1.0f - al) * pa + al * pb;
            float na = wn[ia], nb = wn[ib];
            wn[ia] = al * na + (1.0f - al) * nb;
            wn[ib] = (1.0f - al) * na + al * nb;
        }
    }

    float local = 0.0f;
#pragma unroll
    for (int i = 0; i < 11; ++i) {
        float ppos = fminf(fmaxf(wp[i], 0.0f), 1.0f);
        float pneg = fminf(fmaxf(wn[i], 0.0f), 1.0f);
        // bce(p_pos,t_pos): t=1 only at i==10 ; bce(p_neg,t_neg): t=1 for i<10
        float tp = (i == 10) ? fmaxf(logf(ppos),        -100.0f)
                             : fmaxf(logf(1.0f - ppos), -100.0f);
        float tn = (i < 10)  ? fmaxf(logf(pneg),        -100.0f)
                             : fmaxf(logf(1.0f - pneg), -100.0f);
        local += tp + tn;
    }

    __shared__ double sred[256];
    sred[threadIdx.x] = (double)local;
    __syncthreads();
#pragma unroll
    for (int st = 128; st > 0; st >>= 1) {
        if (threadIdx.x < st) sred[threadIdx.x] += sred[threadIdx.x + st];
        __syncthreads();
    }
    if (threadIdx.x == 0) atomicAdd(&g_acc, sred[0]);
}

__global__ void writeout_kernel(float* __restrict__ out) {
    // final = (loss1 + loss2)/2 = -(S1p+S1n+S2p+S2n) / (4 * 11 * B)
    out[0] = (float)(-g_acc / (4.0 * 11.0 * (double)BN));
}

extern "C" void kernel_launch(void* const* d_in, const int* in_sizes, int n_in,
                              void* d_out, int out_size) {
    const float* aug1 = (const float*)d_in[0];
    const float* aug2 = (const float*)d_in[1];
    float* out = (float*)d_out;

    zero_kernel<<<1, 1>>>();

    normalize_kernel<<<(BN * 32) / 256, 256>>>(aug1, 0);
    normalize_kernel<<<(BN * 32) / 256, 256>>>(aug2, 1);
    pos_kernel<<<(BN * 32) / 256, 256>>>();

    dim3 gram_grid((BN / TPB) * NCHUNK, 2);
    gram_topk_kernel<<<gram_grid, TPB>>>();

    finalize_kernel<<<(2 * BN) / 256, 256>>>();
    writeout_kernel<<<1, 1>>>(out);
}

// round 13
// speedup vs baseline: 3.9203x; 3.9203x over previous
#include <cuda_runtime.h>
#include <cuda_bf16.h>

// GroCo loss v6 — tensor-core Gram via base-ISA mma.sync (HMMA path).
// R12 showed the harness targets compute_103 (no 'a'): tcgen05/TMEM are
// unavailable. mma.sync.m16n8k16.bf16 + ldmatrix + cp.async are sm_80-era
// PTX and compile for the base target, and accumulators stay in registers
// so the fused top-10 needs no epilogue memory at all.
//
// grid=128 (dir*64 + i_tile), 256 thr. Warp w owns rows w*16..w*16+15.
// A tile resident (XOR-swizzled SMEM -> 32 a-frag regs). 64 j-tiles:
// cp.async double-buffered B; per tile 64 ldmatrix.x4 + 128 HMMA per warp;
// c-frags folded into per-lane top-10 (2 rows x 32 cols each); quad
// butterfly merge; soft odd-even sort + BCE inline; atomicAdd(double).

#define BN 8192
#define DD 128
#define NTJ 64

__device__ float          g_n[2][BN * DD];
__device__ __nv_bfloat16  g_nb[2][BN * DD];
__device__ float          g_pos[BN];
__device__ double         g_acc;

// ---------------- helpers ----------------
__device__ __forceinline__ unsigned s2u(const void* p) {
    unsigned a;
    asm("{ .reg .u64 t; cvta.to.shared.u64 t, %1; cvt.u32.u64 %0, t; }"
        : "=r"(a) : "l"(p));
    return a;
}

// swizzled SMEM address for (row, 16B chunk) of a 128x128 bf16 tile:
// row stride 256B, chunk index XORed with row&7 -> ldmatrix conflict-free.
__device__ __forceinline__ unsigned sw_addr(unsigned base, int row, int chunk) {
    return base + (unsigned)(row << 8) + (unsigned)(((chunk ^ (row & 7)) << 4));
}

// cp.async one 128x128 bf16 tile (row-major global) into swizzled SMEM.
__device__ __forceinline__ void cpasync_tile(unsigned sb,
                                             const __nv_bfloat16* src, int tid) {
    const char* s = (const char*)src;
#pragma unroll
    for (int i = 0; i < 8; ++i) {            // 2048 chunks / 256 threads
        int c = tid + (i << 8);
        int row = c >> 4, chunk = c & 15;
        unsigned dst = sw_addr(sb, row, chunk);
        asm volatile("cp.async.cg.shared.global [%0], [%1], 16;"
                     :: "r"(dst), "l"(s + c * 16) : "memory");
    }
}

// Branchless insert into ascending top-10 (t[0] = smallest kept).
__device__ __forceinline__ void topk_insert10(float (&t)[10], float v) {
#pragma unroll
    for (int k = 0; k < 9; ++k) t[k] = fminf(fmaxf(v, t[k]), t[k + 1]);
    t[9] = fmaxf(v, t[9]);
}

// per-row finalize: soft odd-even sort (steepness=1) + BCE term sum.
__device__ __forceinline__ float row_loss(const float (&tt)[10], float pos) {
    float s[11];
#pragma unroll
    for (int k = 0; k < 10; ++k) s[k] = tt[k];
    s[10] = pos;

    const float INV_PI = 0.3183098861837907f;
    float alpha[55];
#pragma unroll
    for (int layer = 0; layer < 11; ++layer) {
        int off = layer & 1;
#pragma unroll
        for (int pi = 0; pi < 5; ++pi) {
            int ia = off + 2 * pi, ib = ia + 1;
            float av = s[ia], bv = s[ib];
            float al = atanf(bv - av) * INV_PI + 0.5f;
            alpha[layer * 5 + pi] = al;
            s[ia] = al * av + (1.0f - al) * bv;
            s[ib] = (1.0f - al) * av + al * bv;
        }
    }
    float wp[11], wn[11];
#pragma unroll
    for (int k = 0; k < 11; ++k) { wp[k] = 0.0f; wn[k] = 1.0f; }
    wp[10] = 1.0f; wn[10] = 0.0f;
#pragma unroll
    for (int layer = 10; layer >= 0; --layer) {
        int off = layer & 1;
#pragma unroll
        for (int pi = 0; pi < 5; ++pi) {
            int ia = off + 2 * pi, ib = ia + 1;
            float al = alpha[layer * 5 + pi];
            float pa = wp[ia], pb = wp[ib];
            wp[ia] = al * pa + (1.0f - al) * pb;
            wp[ib] = (1.0f - al) * pa + al * pb;
            float na = wn[ia], nb2 = wn[ib];
            wn[ia] = al * na + (1.0f - al) * nb2;
            wn[ib] = (1.0f - al) * na + al * nb2;
        }
    }
    float local = 0.0f;
#pragma unroll
    for (int i = 0; i < 11; ++i) {
        float ppos = fminf(fmaxf(wp[i], 0.0f), 1.0f);
        float pneg = fminf(fmaxf(wn[i], 0.0f), 1.0f);
        float tp = (i == 10) ? fmaxf(logf(ppos),        -100.0f)
                             : fmaxf(logf(1.0f - ppos), -100.0f);
        float tn = (i < 10)  ? fmaxf(logf(pneg),        -100.0f)
                             : fmaxf(logf(1.0f - pneg), -100.0f);
        local += tp + tn;
    }
    return local;
}

// ---------------- kernels ----------------
__global__ void zero_kernel() { g_acc = 0.0; }

__global__ void normalize_kernel(const float* __restrict__ x, int dir) {
    int gw   = (blockIdx.x * blockDim.x + threadIdx.x) >> 5;  // warp per row
    int lane = threadIdx.x & 31;
    if (gw >= BN) return;
    float4 v = reinterpret_cast<const float4*>(x)[gw * (DD / 4) + lane];
    float s = v.x * v.x + v.y * v.y + v.z * v.z + v.w * v.w;
#pragma unroll
    for (int o = 16; o > 0; o >>= 1) s += __shfl_xor_sync(0xffffffffu, s, o);
    float inv = 1.0f / fmaxf(sqrtf(s), 1e-8f);
    float4 o4 = make_float4(v.x * inv, v.y * inv, v.z * inv, v.w * inv);
    reinterpret_cast<float4*>(g_n[dir])[gw * (DD / 4) + lane] = o4;
    __nv_bfloat162 lo = __floats2bfloat162_rn(o4.x, o4.y);
    __nv_bfloat162 hi = __floats2bfloat162_rn(o4.z, o4.w);
    uint2 pk;
    pk.x = *reinterpret_cast<unsigned*>(&lo);
    pk.y = *reinterpret_cast<unsigned*>(&hi);
    reinterpret_cast<uint2*>(g_nb[dir])[gw * 32 + lane] = pk;
}

__global__ void pos_kernel() {
    int gw   = (blockIdx.x * blockDim.x + threadIdx.x) >> 5;
    int lane = threadIdx.x & 31;
    if (gw >= BN) return;
    float4 a = reinterpret_cast<const float4*>(g_n[0])[gw * (DD / 4) + lane];
    float4 b = reinterpret_cast<const float4*>(g_n[1])[gw * (DD / 4) + lane];
    float s = a.x * b.x + a.y * b.y + a.z * b.z + a.w * b.w;
#pragma unroll
    for (int o = 16; o > 0; o >>= 1) s += __shfl_xor_sync(0xffffffffu, s, o);
    if (lane == 0) g_pos[gw] = s;
}

// SMEM: A @0 (32KB), B0 @32768, B1 @65536, sred @98304 (2KB)
#define SMEM_DYN (98304 + 2048)

__global__ void __launch_bounds__(256, 1) gram_kernel() {
    extern __shared__ char smem[];
    unsigned sbase = s2u(smem);
    double* sred = (double*)(smem + 98304);
    int tid = threadIdx.x, w = tid >> 5, l = tid & 31;
    int dir = blockIdx.x >> 6, it = blockIdx.x & 63;
    const __nv_bfloat16* nb = g_nb[dir];

    // prologue: A tile + B tile 0
    cpasync_tile(sbase, nb + (size_t)it * 128 * DD, tid);
    cpasync_tile(sbase + 32768, nb, tid);
    asm volatile("cp.async.commit_group;" ::: "memory");
    asm volatile("cp.async.wait_group 0;" ::: "memory");
    __syncthreads();

    // A fragments: 8 k-atoms, resident. m16n8k16 A-frag via ldmatrix.x4:
    // groups g0..g3 -> (m+0,k0),(m+8,k0),(m+0,k8),(m+8,k8)
    unsigned af[8][4];
    {
        int g = l >> 3, ri = l & 7;
        int arow = w * 16 + ((g & 1) << 3) + ri;
        int cadd = g >> 1;
#pragma unroll
        for (int ka = 0; ka < 8; ++ka) {
            unsigned ad = sw_addr(sbase, arow, ka * 2 + cadd);
            asm volatile(
                "ldmatrix.sync.aligned.m8n8.x4.shared.b16 {%0,%1,%2,%3}, [%4];"
                : "=r"(af[ka][0]), "=r"(af[ka][1]), "=r"(af[ka][2]), "=r"(af[ka][3])
                : "r"(ad));
        }
    }

    float t0[10], t1[10];
#pragma unroll
    for (int k = 0; k < 10; ++k) { t0[k] = -1e30f; t1[k] = -1e30f; }
    int r0 = it * 128 + w * 16 + (l >> 2);
    int r1 = r0 + 8;
    int brow = l & 7;         // b-frag row-in-atom
    int bchunk = l >> 3;      // 0..3: (ka lo/hi) x (k half)
    int cbase = (l & 3) << 1; // col offset within n-atom for c-frag

#pragma unroll 1
    for (int jt = 0; jt < NTJ; ++jt) {
        unsigned bs = sbase + 32768 + (unsigned)((jt & 1) << 15);
        if (jt + 1 < NTJ) {  // prefetch next B into the other buffer
            cpasync_tile(sbase + 32768 + (unsigned)(((jt + 1) & 1) << 15),
                         nb + (size_t)(jt + 1) * 128 * DD, tid);
            asm volatile("cp.async.commit_group;" ::: "memory");
        }

        float acc[16][4];
#pragma unroll
        for (int n = 0; n < 16; ++n) {
#pragma unroll
            for (int p = 0; p < 4; ++p) {
                unsigned b0, b1, b2, b3;
                unsigned bd = sw_addr(bs, (n << 3) + brow, (p << 2) + bchunk);
                asm volatile(
                    "ldmatrix.sync.aligned.m8n8.x4.shared.b16 {%0,%1,%2,%3}, [%4];"
                    : "=r"(b0), "=r"(b1), "=r"(b2), "=r"(b3) : "r"(bd));
                if (p == 0) {
                    asm volatile(
                        "mma.sync.aligned.m16n8k16.row.col.f32.bf16.bf16.f32 "
                        "{%0,%1,%2,%3}, {%4,%5,%6,%7}, {%8,%9}, {%10,%10,%10,%10};"
                        : "=f"(acc[n][0]), "=f"(acc[n][1]),
                          "=f"(acc[n][2]), "=f"(acc[n][3])
                        : "r"(af[0][0]), "r"(af[0][1]), "r"(af[0][2]), "r"(af[0][3]),
                          "r"(b0), "r"(b1), "f"(0.0f));
                } else {
                    asm volatile(
                        "mma.sync.aligned.m16n8k16.row.col.f32.bf16.bf16.f32 "
                        "{%0,%1,%2,%3}, {%4,%5,%6,%7}, {%8,%9}, {%0,%1,%2,%3};"
                        : "+f"(acc[n][0]), "+f"(acc[n][1]),
                          "+f"(acc[n][2]), "+f"(acc[n][3])
                        : "r"(af[2 * p][0]), "r"(af[2 * p][1]),
                          "r"(af[2 * p][2]), "r"(af[2 * p][3]),
                          "r"(b0), "r"(b1));
                }
                asm volatile(
                    "mma.sync.aligned.m16n8k16.row.col.f32.bf16.bf16.f32 "
                    "{%0,%1,%2,%3}, {%4,%5,%6,%7}, {%8,%9}, {%0,%1,%2,%3};"
                    : "+f"(acc[n][0]), "+f"(acc[n][1]),
                      "+f"(acc[n][2]), "+f"(acc[n][3])
                    : "r"(af[2 * p + 1][0]), "r"(af[2 * p + 1][1]),
                      "r"(af[2 * p + 1][2]), "r"(af[2 * p + 1][3]),
                      "r"(b2), "r"(b3));
            }
        }

        // fold this tile's sims into per-lane top-10 (2 rows x 32 cols)
        int jb = jt * 128 + cbase;
#pragma unroll
        for (int n = 0; n < 16; ++n) {
            int j0 = jb + (n << 3), j1 = j0 + 1;
            float v;
            v = acc[n][0]; if (v > t0[0] && j0 != r0) topk_insert10(t0, v);
            v = acc[n][1]; if (v > t0[0] && j1 != r0) topk_insert10(t0, v);
            v = acc[n][2]; if (v > t1[0] && j0 != r1) topk_insert10(t1, v);
            v = acc[n][3]; if (v > t1[0] && j1 != r1) topk_insert10(t1, v);
        }

        if (jt + 1 < NTJ)
            asm volatile("cp.async.wait_group 0;" ::: "memory");
        __syncthreads();
    }

    // quad butterfly merge (lanes 4q..4q+3 share rows). Snapshot before each
    // exchange: partners' live arrays mutate mid-step, snapshots don't.
#pragma unroll
    for (int step = 1; step <= 2; step <<= 1) {
        float s0[10], s1[10];
#pragma unroll
        for (int k = 0; k < 10; ++k) { s0[k] = t0[k]; s1[k] = t1[k]; }
#pragma unroll
        for (int k = 0; k < 10; ++k) {
            float v0 = __shfl_xor_sync(0xffffffffu, s0[k], step);
            float v1 = __shfl_xor_sync(0xffffffffu, s1[k], step);
            if (v0 > t0[0]) topk_insert10(t0, v0);
            if (v1 > t1[0]) topk_insert10(t1, v1);
        }
    }

    float local = 0.0f;
    if ((l & 3) == 0) {
        local  = row_loss(t0, g_pos[r0]);
        local += row_loss(t1, g_pos[r1]);
    }
    sred[tid] = (double)local;
    __syncthreads();
#pragma unroll
    for (int st = 128; st > 0; st >>= 1) {
        if (tid < st) sred[tid] += sred[tid + st];
        __syncthreads();
    }
    if (tid == 0) atomicAdd(&g_acc, sred[0]);
}

__global__ void writeout_kernel(float* __restrict__ out) {
    out[0] = (float)(-g_acc / (4.0 * 11.0 * (double)BN));
}

extern "C" void kernel_launch(void* const* d_in, const int* in_sizes, int n_in,
                              void* d_out, int out_size) {
    const float* aug1 = (const float*)d_in[0];
    const float* aug2 = (const float*)d_in[1];
    float* out = (float*)d_out;

    cudaFuncSetAttribute(gram_kernel,
                         cudaFuncAttributeMaxDynamicSharedMemorySize, SMEM_DYN);

    zero_kernel<<<1, 1>>>();
    normalize_kernel<<<(BN * 32) / 256, 256>>>(aug1, 0);
    normalize_kernel<<<(BN * 32) / 256, 256>>>(aug2, 1);
    pos_kernel<<<(BN * 32) / 256, 256>>>();
    gram_kernel<<<128, 256, SMEM_DYN>>>();
    writeout_kernel<<<1, 1>>>(out);
}